// round 14
// baseline (speedup 1.0000x reference)
#include <cuda_runtime.h>
#include <cuda_bf16.h>
#include <cstdint>

#define N_NODES 50000
#define N_EDGES 800000
#define F_IN    128
#define HIDDEN  256
#define N_GRAPHS 128
#define BUCKET  64   // max in-degree; P(overflow) ~ 1e-17 for Binom(800k, 1/50k)

// ---------------- scratch (static device globals; no allocation) ----------------
__device__ float g_bufA[N_NODES * HIDDEN];   // h1 (fp32)
__device__ float g_bufB[N_NODES * HIDDEN];   // h2 (fp32)
__device__ __align__(16) __nv_bfloat16 g_sHi[N_NODES * HIDDEN];  // spmm out hi
__device__ __align__(16) __nv_bfloat16 g_sLo[N_NODES * HIDDEN];  // spmm out lo
__device__ int   g_fill[N_NODES];
__device__ int2  g_csr[N_NODES * BUCKET];    // (src, w-bits)
__device__ int   g_gstart[N_GRAPHS + 1];
// weights transposed to [N][K] K-major, bf16 hi/lo split
__device__ __align__(16) __nv_bfloat16 g_W1hi[HIDDEN * F_IN];
__device__ __align__(16) __nv_bfloat16 g_W1lo[HIDDEN * F_IN];
__device__ __align__(16) __nv_bfloat16 g_W2hi[HIDDEN * HIDDEN];
__device__ __align__(16) __nv_bfloat16 g_W2lo[HIDDEN * HIDDEN];

// ---------------- fused setup ----------------
__global__ void k_setup(const int* __restrict__ seg_ids,
                        const float* __restrict__ W1,
                        const float* __restrict__ W2) {
    int i = blockIdx.x * blockDim.x + threadIdx.x;
    if (i < N_NODES) {
        g_fill[i] = 0;
        int s = seg_ids[i];
        int p = (i > 0) ? seg_ids[i - 1] : -1;
        for (int g = p + 1; g <= s; g++) g_gstart[g] = i;
        if (i == N_NODES - 1)
            for (int g = s + 1; g <= N_GRAPHS; g++) g_gstart[g] = N_NODES;
    }
    if (i < HIDDEN * F_IN) {
        int n = i / F_IN, k = i % F_IN;
        float v = W1[k * HIDDEN + n];
        __nv_bfloat16 h = __float2bfloat16_rn(v);
        g_W1hi[n * F_IN + k] = h;
        g_W1lo[n * F_IN + k] = __float2bfloat16_rn(v - __bfloat162float(h));
    }
    if (i < HIDDEN * HIDDEN) {
        int n = i / HIDDEN, k = i % HIDDEN;
        float v = W2[k * HIDDEN + n];
        __nv_bfloat16 h = __float2bfloat16_rn(v);
        g_W2hi[n * HIDDEN + k] = h;
        g_W2lo[n * HIDDEN + k] = __float2bfloat16_rn(v - __bfloat162float(h));
    }
}

__global__ void k_scatter(const int* __restrict__ edge_src,
                          const int* __restrict__ edge_dst,
                          const float* __restrict__ edge_w) {
    int e = blockIdx.x * blockDim.x + threadIdx.x;
    if (e >= N_EDGES) return;
    int d = edge_dst[e];
    int pos = atomicAdd(&g_fill[d], 1);
    if (pos < BUCKET)
        g_csr[d * BUCKET + pos] = make_int2(edge_src[e], __float_as_int(edge_w[e]));
}

// ---------------- ptx helpers ----------------
__device__ __forceinline__ void cp16(uint32_t dst, const void* src, bool v) {
    asm volatile("cp.async.ca.shared.global [%0], [%1], 16, %2;"
                 :: "r"(dst), "l"(src), "r"(v ? 16 : 0) : "memory");
}
__device__ __forceinline__ void ldsm4(uint32_t* r, uint32_t a) {
    asm volatile("ldmatrix.sync.aligned.m8n8.x4.shared.b16 {%0,%1,%2,%3}, [%4];"
                 : "=r"(r[0]), "=r"(r[1]), "=r"(r[2]), "=r"(r[3]) : "r"(a));
}
__device__ __forceinline__ void ldsm2(uint32_t* r, uint32_t a) {
    asm volatile("ldmatrix.sync.aligned.m8n8.x2.shared.b16 {%0,%1}, [%2];"
                 : "=r"(r[0]), "=r"(r[1]) : "r"(a));
}

// ---------------- bf16x3 pipelined tensor GEMM ----------------
// C = relu(A(hi,lo)[M,K] @ W(hi,lo)[K,256] + bias)
// 128x128 tile, BK=16 (small stage => 2 CTAs/SM), 256 threads (8 warps 2Mx4N),
// warp tile 64x32. 2-stage cp.async pipeline; ldmatrix; m16n8k16 bf16 MMA.
#define GBM 128
#define GBN 128
#define GBK 16
#define TS 24                          // bf16 row stride (16 + 8 pad) = 48B (16B-mult)
#define ARR_BYTES (128 * TS * 2)       // 6144 B
#define STAGE_BYTES (4 * ARR_BYTES)    // 24576 B
#define OFF_AHI 0
#define OFF_ALO ARR_BYTES
#define OFF_BHI (2 * ARR_BYTES)
#define OFF_BLO (3 * ARR_BYTES)
#define GEMM_SMEM (2 * STAGE_BYTES)    // 49152 B -> 2 CTAs/SM

__global__ __launch_bounds__(256, 2) void k_gemm_pipe(
        const __nv_bfloat16* __restrict__ Ahi,
        const __nv_bfloat16* __restrict__ Alo, int K,
        const __nv_bfloat16* __restrict__ Whi,
        const __nv_bfloat16* __restrict__ Wlo,
        const float* __restrict__ bias,
        float* __restrict__ C, int M) {
    extern __shared__ __align__(16) __nv_bfloat16 smem[];
    uint32_t smb = (uint32_t)__cvta_generic_to_shared(smem);

    int tid  = threadIdx.x;
    int lane = tid & 31;
    int warp = tid >> 5;
    int wm = warp & 1;        // M offset 0/64
    int wn = warp >> 1;       // N offset 0/32/64/96

    int rowBase = blockIdx.y * GBM;
    int colBase = blockIdx.x * GBN;

    float acc[4][4][4];
#pragma unroll
    for (int mi = 0; mi < 4; mi++)
#pragma unroll
        for (int ni = 0; ni < 4; ni++)
#pragma unroll
            for (int r = 0; r < 4; r++) acc[mi][ni][r] = 0.0f;

    int ldrow = tid >> 1;            // 0..127
    int ldk   = (tid & 1) * 8;       // 0 or 8 (8 bf16 = 16B per array per chunk)
    bool aValid = (rowBase + ldrow) < M;
    const __nv_bfloat16* aHiSrc = Ahi + (long)(rowBase + ldrow) * K + ldk;
    const __nv_bfloat16* aLoSrc = Alo + (long)(rowBase + ldrow) * K + ldk;
    const __nv_bfloat16* bHiSrc = Whi + (long)(colBase + ldrow) * K + ldk;
    const __nv_bfloat16* bLoSrc = Wlo + (long)(colBase + ldrow) * K + ldk;
    uint32_t dstOff = (uint32_t)(ldrow * TS + ldk) * 2;

    int nT = K / GBK;

    // prologue: stage 0
    {
        uint32_t base = smb;
        cp16(base + OFF_AHI + dstOff, aHiSrc, aValid);
        cp16(base + OFF_ALO + dstOff, aLoSrc, aValid);
        cp16(base + OFF_BHI + dstOff, bHiSrc, true);
        cp16(base + OFF_BLO + dstOff, bLoSrc, true);
        asm volatile("cp.async.commit_group;" ::: "memory");
    }

    // fragment address offsets (constant across chunks)
    uint32_t aoff = (uint32_t)(((wm * 64) + (lane & 15)) * TS + ((lane >> 4) << 3)) * 2;
    uint32_t boff = (uint32_t)(((wn * 32) + (lane & 7)) * TS + (((lane >> 3) & 1) << 3)) * 2;

    for (int ch = 0; ch < nT; ch++) {
        if (ch + 1 < nT) {
            int kt = (ch + 1) * GBK;
            uint32_t base = smb + ((ch + 1) & 1) * STAGE_BYTES;
            cp16(base + OFF_AHI + dstOff, aHiSrc + kt, aValid);
            cp16(base + OFF_ALO + dstOff, aLoSrc + kt, aValid);
            cp16(base + OFF_BHI + dstOff, bHiSrc + kt, true);
            cp16(base + OFF_BLO + dstOff, bLoSrc + kt, true);
            asm volatile("cp.async.commit_group;" ::: "memory");
            asm volatile("cp.async.wait_group 1;" ::: "memory");
        } else {
            asm volatile("cp.async.wait_group 0;" ::: "memory");
        }
        __syncthreads();

        uint32_t st = smb + (ch & 1) * STAGE_BYTES;
        uint32_t ah[4][4], al[4][4], bh[4][2], bl[4][2];
#pragma unroll
        for (int mi = 0; mi < 4; mi++) {
            uint32_t ro = aoff + (uint32_t)(mi * 16 * TS) * 2;
            ldsm4(ah[mi], st + OFF_AHI + ro);
            ldsm4(al[mi], st + OFF_ALO + ro);
        }
#pragma unroll
        for (int ni = 0; ni < 4; ni++) {
            uint32_t ro = boff + (uint32_t)(ni * 8 * TS) * 2;
            ldsm2(bh[ni], st + OFF_BHI + ro);
            ldsm2(bl[ni], st + OFF_BLO + ro);
        }
#define MMA_B(AF, BF)                                                          \
        asm volatile(                                                          \
            "mma.sync.aligned.m16n8k16.row.col.f32.bf16.bf16.f32 "             \
            "{%0,%1,%2,%3}, {%4,%5,%6,%7}, {%8,%9}, {%0,%1,%2,%3};"            \
            : "+f"(acc[mi][ni][0]), "+f"(acc[mi][ni][1]),                      \
              "+f"(acc[mi][ni][2]), "+f"(acc[mi][ni][3])                       \
            : "r"(AF[mi][0]), "r"(AF[mi][1]),                                  \
              "r"(AF[mi][2]), "r"(AF[mi][3]),                                  \
              "r"(BF[ni][0]), "r"(BF[ni][1]))
#pragma unroll
        for (int mi = 0; mi < 4; mi++)
#pragma unroll
            for (int ni = 0; ni < 4; ni++) { MMA_B(al, bh); }
#pragma unroll
        for (int mi = 0; mi < 4; mi++)
#pragma unroll
            for (int ni = 0; ni < 4; ni++) { MMA_B(ah, bl); }
#pragma unroll
        for (int mi = 0; mi < 4; mi++)
#pragma unroll
            for (int ni = 0; ni < 4; ni++) { MMA_B(ah, bh); }
#undef MMA_B
        __syncthreads();
    }

    // epilogue: bias + relu + store (m16n8 accum layout)
#pragma unroll
    for (int mi = 0; mi < 4; mi++) {
        int r0 = rowBase + wm * 64 + mi * 16 + (lane >> 2);
#pragma unroll
        for (int ni = 0; ni < 4; ni++) {
            int col = colBase + wn * 32 + ni * 8 + (lane & 3) * 2;
            float b0 = bias[col], b1v = bias[col + 1];
            if (r0 < M) {
                float2 o;
                o.x = fmaxf(acc[mi][ni][0] + b0, 0.f);
                o.y = fmaxf(acc[mi][ni][1] + b1v, 0.f);
                *(float2*)&C[(long)r0 * HIDDEN + col] = o;
            }
            if (r0 + 8 < M) {
                float2 o;
                o.x = fmaxf(acc[mi][ni][2] + b0, 0.f);
                o.y = fmaxf(acc[mi][ni][3] + b1v, 0.f);
                *(float2*)&C[(long)(r0 + 8) * HIDDEN + col] = o;
            }
        }
    }
}

// ---------------- SpMM: fp32 gather-accumulate -> bf16 hi/lo output ----------------
__device__ __forceinline__ void store_hilo(__nv_bfloat16* hi, __nv_bfloat16* lo,
                                           long off, float4 acc) {
    __nv_bfloat16 hx = __float2bfloat16_rn(acc.x);
    __nv_bfloat16 hy = __float2bfloat16_rn(acc.y);
    __nv_bfloat16 hz = __float2bfloat16_rn(acc.z);
    __nv_bfloat16 hw = __float2bfloat16_rn(acc.w);
    __nv_bfloat162 h01; h01.x = hx; h01.y = hy;
    __nv_bfloat162 h23; h23.x = hz; h23.y = hw;
    __nv_bfloat162 l01, l23;
    l01.x = __float2bfloat16_rn(acc.x - __bfloat162float(hx));
    l01.y = __float2bfloat16_rn(acc.y - __bfloat162float(hy));
    l23.x = __float2bfloat16_rn(acc.z - __bfloat162float(hz));
    l23.y = __float2bfloat16_rn(acc.w - __bfloat162float(hw));
    *(__nv_bfloat162*)&hi[off]     = h01;
    *(__nv_bfloat162*)&hi[off + 2] = h23;
    *(__nv_bfloat162*)&lo[off]     = l01;
    *(__nv_bfloat162*)&lo[off + 2] = l23;
}

// 128-col: 1 warp per node (input fp32 x)
__global__ __launch_bounds__(256) void k_spmm128(const float* __restrict__ in,
                                                 __nv_bfloat16* __restrict__ outHi,
                                                 __nv_bfloat16* __restrict__ outLo) {
    int node = blockIdx.x * 8 + (threadIdx.x >> 5);
    if (node >= N_NODES) return;
    int c = (threadIdx.x & 31) * 4;
    int beg = node * BUCKET;
    int end = beg + g_fill[node];

    float4 acc = make_float4(0.f, 0.f, 0.f, 0.f);
    int e = beg;
    for (; e + 4 <= end; e += 4) {
        int4 p = *(const int4*)&g_csr[e];
        int4 q = *(const int4*)&g_csr[e + 2];
        float w0 = __int_as_float(p.y), w1 = __int_as_float(p.w);
        float w2 = __int_as_float(q.y), w3 = __int_as_float(q.w);
        float4 v0 = *(const float4*)&in[(long)p.x * F_IN + c];
        float4 v1 = *(const float4*)&in[(long)p.z * F_IN + c];
        float4 v2 = *(const float4*)&in[(long)q.x * F_IN + c];
        float4 v3 = *(const float4*)&in[(long)q.z * F_IN + c];
        acc.x = fmaf(v0.x, w0, acc.x); acc.y = fmaf(v0.y, w0, acc.y);
        acc.z = fmaf(v0.z, w0, acc.z); acc.w = fmaf(v0.w, w0, acc.w);
        acc.x = fmaf(v1.x, w1, acc.x); acc.y = fmaf(v1.y, w1, acc.y);
        acc.z = fmaf(v1.z, w1, acc.z); acc.w = fmaf(v1.w, w1, acc.w);
        acc.x = fmaf(v2.x, w2, acc.x); acc.y = fmaf(v2.y, w2, acc.y);
        acc.z = fmaf(v2.z, w2, acc.z); acc.w = fmaf(v2.w, w2, acc.w);
        acc.x = fmaf(v3.x, w3, acc.x); acc.y = fmaf(v3.y, w3, acc.y);
        acc.z = fmaf(v3.z, w3, acc.z); acc.w = fmaf(v3.w, w3, acc.w);
    }
    for (; e < end; e++) {
        int2 p = g_csr[e];
        float w = __int_as_float(p.y);
        float4 v = *(const float4*)&in[(long)p.x * F_IN + c];
        acc.x = fmaf(v.x, w, acc.x); acc.y = fmaf(v.y, w, acc.y);
        acc.z = fmaf(v.z, w, acc.z); acc.w = fmaf(v.w, w, acc.w);
    }
    store_hilo(outHi, outLo, (long)node * F_IN + c, acc);
}

// 256-col: 64 threads per node (input fp32 h1)
__global__ __launch_bounds__(256) void k_spmm256(const float* __restrict__ in,
                                                 __nv_bfloat16* __restrict__ outHi,
                                                 __nv_bfloat16* __restrict__ outLo) {
    int node = blockIdx.x * 4 + (threadIdx.x >> 6);
    if (node >= N_NODES) return;
    int c = (threadIdx.x & 63) * 4;
    int beg = node * BUCKET;
    int end = beg + g_fill[node];

    float4 acc = make_float4(0.f, 0.f, 0.f, 0.f);
    int e = beg;
    for (; e + 4 <= end; e += 4) {
        int4 p = *(const int4*)&g_csr[e];
        int4 q = *(const int4*)&g_csr[e + 2];
        float w0 = __int_as_float(p.y), w1 = __int_as_float(p.w);
        float w2 = __int_as_float(q.y), w3 = __int_as_float(q.w);
        float4 v0 = *(const float4*)&in[(long)p.x * HIDDEN + c];
        float4 v1 = *(const float4*)&in[(long)p.z * HIDDEN + c];
        float4 v2 = *(const float4*)&in[(long)q.x * HIDDEN + c];
        float4 v3 = *(const float4*)&in[(long)q.z * HIDDEN + c];
        acc.x = fmaf(v0.x, w0, acc.x); acc.y = fmaf(v0.y, w0, acc.y);
        acc.z = fmaf(v0.z, w0, acc.z); acc.w = fmaf(v0.w, w0, acc.w);
        acc.x = fmaf(v1.x, w1, acc.x); acc.y = fmaf(v1.y, w1, acc.y);
        acc.z = fmaf(v1.z, w1, acc.z); acc.w = fmaf(v1.w, w1, acc.w);
        acc.x = fmaf(v2.x, w2, acc.x); acc.y = fmaf(v2.y, w2, acc.y);
        acc.z = fmaf(v2.z, w2, acc.z); acc.w = fmaf(v2.w, w2, acc.w);
        acc.x = fmaf(v3.x, w3, acc.x); acc.y = fmaf(v3.y, w3, acc.y);
        acc.z = fmaf(v3.z, w3, acc.z); acc.w = fmaf(v3.w, w3, acc.w);
    }
    for (; e < end; e++) {
        int2 p = g_csr[e];
        float w = __int_as_float(p.y);
        float4 v = *(const float4*)&in[(long)p.x * HIDDEN + c];
        acc.x = fmaf(v.x, w, acc.x); acc.y = fmaf(v.y, w, acc.y);
        acc.z = fmaf(v.z, w, acc.z); acc.w = fmaf(v.w, w, acc.w);
    }
    store_hilo(outHi, outLo, (long)node * HIDDEN + c, acc);
}

// ---------------- fused pool + head ----------------
__global__ __launch_bounds__(256) void k_poolhead(const float* __restrict__ h,
                                                  const float* __restrict__ Wd,
                                                  const float* __restrict__ bd,
                                                  const float* __restrict__ Wo,
                                                  const float* __restrict__ bo,
                                                  float* __restrict__ out) {
    __shared__ float pg[HIDDEN];
    __shared__ float red[256];
    int g = blockIdx.x;
    int j = threadIdx.x;
    int beg = g_gstart[g], end = g_gstart[g + 1];

    float acc0 = 0.f, acc1 = 0.f, acc2 = 0.f, acc3 = 0.f;
    int n = beg;
    for (; n + 4 <= end; n += 4) {
        acc0 += h[(long)n * HIDDEN + j];
        acc1 += h[(long)(n + 1) * HIDDEN + j];
        acc2 += h[(long)(n + 2) * HIDDEN + j];
        acc3 += h[(long)(n + 3) * HIDDEN + j];
    }
    for (; n < end; n++) acc0 += h[(long)n * HIDDEN + j];
    pg[j] = (acc0 + acc1) + (acc2 + acc3);
    __syncthreads();

    float acc = 0.f;
#pragma unroll 8
    for (int k = 0; k < HIDDEN; k++)
        acc = fmaf(pg[k], Wd[k * HIDDEN + j], acc);
    float v = fmaxf(acc + bd[j], 0.f);
    red[j] = v * Wo[j];
    __syncthreads();
    for (int s = 128; s > 0; s >>= 1) {
        if (j < s) red[j] += red[j + s];
        __syncthreads();
    }
    if (j == 0) out[g] = red[0] + bo[0];
}

// ---------------- launch ----------------
extern "C" void kernel_launch(void* const* d_in, const int* in_sizes, int n_in,
                              void* d_out, int out_size) {
    const float* x        = (const float*)d_in[0];
    const int*   edge_src = (const int*)d_in[1];
    const int*   edge_dst = (const int*)d_in[2];
    const float* edge_w   = (const float*)d_in[3];
    const int*   seg_ids  = (const int*)d_in[4];
    const float* W1       = (const float*)d_in[5];
    const float* b1       = (const float*)d_in[6];
    const float* W2       = (const float*)d_in[7];
    const float* b2       = (const float*)d_in[8];
    const float* Wd       = (const float*)d_in[9];
    const float* bd       = (const float*)d_in[10];
    const float* Wo       = (const float*)d_in[11];
    const float* bo       = (const float*)d_in[12];
    float* out = (float*)d_out;

    float* bufA; cudaGetSymbolAddress((void**)&bufA, g_bufA);
    float* bufB; cudaGetSymbolAddress((void**)&bufB, g_bufB);
    __nv_bfloat16* sHi; cudaGetSymbolAddress((void**)&sHi, g_sHi);
    __nv_bfloat16* sLo; cudaGetSymbolAddress((void**)&sLo, g_sLo);
    __nv_bfloat16* w1hi; cudaGetSymbolAddress((void**)&w1hi, g_W1hi);
    __nv_bfloat16* w1lo; cudaGetSymbolAddress((void**)&w1lo, g_W1lo);
    __nv_bfloat16* w2hi; cudaGetSymbolAddress((void**)&w2hi, g_W2hi);
    __nv_bfloat16* w2lo; cudaGetSymbolAddress((void**)&w2lo, g_W2lo);

    cudaFuncSetAttribute(k_gemm_pipe, cudaFuncAttributeMaxDynamicSharedMemorySize, GEMM_SMEM);

    // setup + scatter
    k_setup<<<(HIDDEN * HIDDEN + 255) / 256, 256>>>(seg_ids, W1, W2);
    k_scatter<<<(N_EDGES + 255) / 256, 256>>>(edge_src, edge_dst, edge_w);

    dim3 gemmGrid(HIDDEN / GBN, (N_NODES + GBM - 1) / GBM);

    // layer 1: s1 = A@x (bf16 hi/lo); h1 = relu(s1 @ W1 + b1)
    k_spmm128<<<(N_NODES + 7) / 8, 256>>>(x, sHi, sLo);
    k_gemm_pipe<<<gemmGrid, 256, GEMM_SMEM>>>(sHi, sLo, F_IN, w1hi, w1lo, b1, bufA, N_NODES);

    // layer 2: s2 = A@h1 (bf16 hi/lo); h2 = relu(s2 @ W2 + b2)
    k_spmm256<<<(N_NODES + 3) / 4, 256>>>(bufA, sHi, sLo);
    k_gemm_pipe<<<gemmGrid, 256, GEMM_SMEM>>>(sHi, sLo, HIDDEN, w2hi, w2lo, b2, bufB, N_NODES);

    // fused pool + head
    k_poolhead<<<N_GRAPHS, HIDDEN>>>(bufB, Wd, bd, Wo, bo, out);
}

// round 15
// speedup vs baseline: 1.2525x; 1.2525x over previous
#include <cuda_runtime.h>
#include <cuda_fp16.h>
#include <cstdint>

#define N_NODES 50000
#define N_EDGES 800000
#define F_IN    128
#define HIDDEN  256
#define N_GRAPHS 128
#define BUCKET  64   // max in-degree; P(overflow) ~ 1e-17 for Binom(800k, 1/50k)

// ---------------- scratch (static device globals; no allocation) ----------------
__device__ float g_bufA[N_NODES * HIDDEN];   // h1 (fp32)
__device__ float g_bufB[N_NODES * HIDDEN];   // h2 (fp32)
__device__ __align__(16) __half g_sH[N_NODES * HIDDEN];   // spmm out (fp16, GEMM A)
__device__ int   g_fill[N_NODES];
__device__ int2  g_csr[N_NODES * BUCKET];    // (src, w-bits)
__device__ int   g_gstart[N_GRAPHS + 1];
// weights transposed to [N][K] K-major, fp16 hi/lo split
__device__ __align__(16) __half g_W1h[HIDDEN * F_IN];
__device__ __align__(16) __half g_W1l[HIDDEN * F_IN];
__device__ __align__(16) __half g_W2h[HIDDEN * HIDDEN];
__device__ __align__(16) __half g_W2l[HIDDEN * HIDDEN];

// ---------------- fused setup ----------------
__global__ void k_setup(const int* __restrict__ seg_ids,
                        const float* __restrict__ W1,
                        const float* __restrict__ W2) {
    int i = blockIdx.x * blockDim.x + threadIdx.x;
    if (i < N_NODES) {
        g_fill[i] = 0;
        int s = seg_ids[i];
        int p = (i > 0) ? seg_ids[i - 1] : -1;
        for (int g = p + 1; g <= s; g++) g_gstart[g] = i;
        if (i == N_NODES - 1)
            for (int g = s + 1; g <= N_GRAPHS; g++) g_gstart[g] = N_NODES;
    }
    if (i < HIDDEN * F_IN) {
        int n = i / F_IN, k = i % F_IN;
        float v = W1[k * HIDDEN + n];
        __half h = __float2half_rn(v);
        g_W1h[n * F_IN + k] = h;
        g_W1l[n * F_IN + k] = __float2half_rn(v - __half2float(h));
    }
    if (i < HIDDEN * HIDDEN) {
        int n = i / HIDDEN, k = i % HIDDEN;
        float v = W2[k * HIDDEN + n];
        __half h = __float2half_rn(v);
        g_W2h[n * HIDDEN + k] = h;
        g_W2l[n * HIDDEN + k] = __float2half_rn(v - __half2float(h));
    }
}

__global__ void k_scatter(const int* __restrict__ edge_src,
                          const int* __restrict__ edge_dst,
                          const float* __restrict__ edge_w) {
    int e = blockIdx.x * blockDim.x + threadIdx.x;
    if (e >= N_EDGES) return;
    int d = edge_dst[e];
    int pos = atomicAdd(&g_fill[d], 1);
    if (pos < BUCKET)
        g_csr[d * BUCKET + pos] = make_int2(edge_src[e], __float_as_int(edge_w[e]));
}

// ---------------- ptx helpers ----------------
__device__ __forceinline__ void cp16(uint32_t dst, const void* src, bool v) {
    asm volatile("cp.async.ca.shared.global [%0], [%1], 16, %2;"
                 :: "r"(dst), "l"(src), "r"(v ? 16 : 0) : "memory");
}
__device__ __forceinline__ void ldsm4(uint32_t* r, uint32_t a) {
    asm volatile("ldmatrix.sync.aligned.m8n8.x4.shared.b16 {%0,%1,%2,%3}, [%4];"
                 : "=r"(r[0]), "=r"(r[1]), "=r"(r[2]), "=r"(r[3]) : "r"(a));
}
__device__ __forceinline__ void ldsm2(uint32_t* r, uint32_t a) {
    asm volatile("ldmatrix.sync.aligned.m8n8.x2.shared.b16 {%0,%1}, [%2];"
                 : "=r"(r[0]), "=r"(r[1]) : "r"(a));
}

// ---------------- fp16x2 pipelined tensor GEMM ----------------
// C = relu(A[M,K](fp16) @ (Wh+Wl)[K,256](fp16 hi/lo) + bias)
// acc = a*Wl + a*Wh   (error: only A's fp16 rounding, done upstream in SpMM)
// 128x128 tile, BK=32, 3-stage cp.async pipeline, ONE barrier per chunk.
// 256 threads (8 warps 2Mx4N), warp tile 64x32, m16n8k16 fp16 MMA fp32 acc.
#define GBM 128
#define GBN 128
#define GBK 32
#define TS 40                          // fp16 row stride (32 + 8 pad) = 80B
#define ARR_BYTES (128 * TS * 2)       // 10240 B
#define STAGE_BYTES (3 * ARR_BYTES)    // A + Bh + Bl = 30720 B
#define OFF_A  0
#define OFF_BH ARR_BYTES
#define OFF_BL (2 * ARR_BYTES)
#define NSTAGE 3
#define GEMM_SMEM (NSTAGE * STAGE_BYTES)   // 92160 B -> 2 CTAs/SM (180KB/228KB)

__global__ __launch_bounds__(256, 2) void k_gemm_pipe(
        const __half* __restrict__ A, int K,
        const __half* __restrict__ Wh,
        const __half* __restrict__ Wl,
        const float* __restrict__ bias,
        float* __restrict__ C, int M) {
    extern __shared__ __align__(16) __half smem[];
    uint32_t smb = (uint32_t)__cvta_generic_to_shared(smem);

    int tid  = threadIdx.x;
    int lane = tid & 31;
    int warp = tid >> 5;
    int wm = warp & 1;        // M offset 0/64
    int wn = warp >> 1;       // N offset 0/32/64/96

    int rowBase = blockIdx.y * GBM;
    int colBase = blockIdx.x * GBN;

    float acc[4][4][4];
#pragma unroll
    for (int mi = 0; mi < 4; mi++)
#pragma unroll
        for (int ni = 0; ni < 4; ni++)
#pragma unroll
            for (int r = 0; r < 4; r++) acc[mi][ni][r] = 0.0f;

    int ldrow = tid >> 1;            // 0..127
    int ldk   = (tid & 1) * 16;      // 0 or 16 (16 fp16 = 32B per array per chunk)
    bool aValid = (rowBase + ldrow) < M;
    const __half* aSrc  = A  + (long)(rowBase + ldrow) * K + ldk;
    const __half* bhSrc = Wh + (long)(colBase + ldrow) * K + ldk;
    const __half* blSrc = Wl + (long)(colBase + ldrow) * K + ldk;
    uint32_t dstOff = (uint32_t)(ldrow * TS + ldk) * 2;

    int nT = K / GBK;   // 4 or 8

    // prologue: stages 0 and 1
#pragma unroll
    for (int s = 0; s < 2; s++) {
        int kt = s * GBK;
        uint32_t base = smb + s * STAGE_BYTES;
        cp16(base + OFF_A  + dstOff,      aSrc  + kt,     aValid);
        cp16(base + OFF_A  + dstOff + 16, aSrc  + kt + 8, aValid);
        cp16(base + OFF_BH + dstOff,      bhSrc + kt,     true);
        cp16(base + OFF_BH + dstOff + 16, bhSrc + kt + 8, true);
        cp16(base + OFF_BL + dstOff,      blSrc + kt,     true);
        cp16(base + OFF_BL + dstOff + 16, blSrc + kt + 8, true);
        asm volatile("cp.async.commit_group;" ::: "memory");
    }

    // fragment address offsets (constant across chunks)
    uint32_t aoff = (uint32_t)(((wm * 64) + (lane & 15)) * TS + ((lane >> 4) << 3)) * 2;
    uint32_t boff = (uint32_t)(((wn * 32) + (lane & 7)) * TS + (((lane >> 3) & 1) << 3)) * 2;

    int stage = 0;
    for (int ch = 0; ch < nT; ch++) {
        asm volatile("cp.async.wait_group 1;" ::: "memory");
        __syncthreads();   // stage ch ready; all warps done reading stage (ch-1)

        // prefetch chunk ch+2 into stage (ch+2)%3 == stage of (ch-1)
        {
            int pf = ch + 2;
            if (pf < nT) {
                int kt = pf * GBK;
                uint32_t base = smb + (pf % NSTAGE) * STAGE_BYTES;
                cp16(base + OFF_A  + dstOff,      aSrc  + kt,     aValid);
                cp16(base + OFF_A  + dstOff + 16, aSrc  + kt + 8, aValid);
                cp16(base + OFF_BH + dstOff,      bhSrc + kt,     true);
                cp16(base + OFF_BH + dstOff + 16, bhSrc + kt + 8, true);
                cp16(base + OFF_BL + dstOff,      blSrc + kt,     true);
                cp16(base + OFF_BL + dstOff + 16, blSrc + kt + 8, true);
            }
            asm volatile("cp.async.commit_group;" ::: "memory");
        }

        uint32_t st = smb + stage * STAGE_BYTES;
#pragma unroll
        for (int kk = 0; kk < GBK; kk += 16) {
            uint32_t af[4][4], bh[4][2], bl[4][2];
#pragma unroll
            for (int mi = 0; mi < 4; mi++) {
                uint32_t ro = aoff + (uint32_t)(kk + mi * 16 * TS) * 2;
                ldsm4(af[mi], st + OFF_A + ro);
            }
#pragma unroll
            for (int ni = 0; ni < 4; ni++) {
                uint32_t ro = boff + (uint32_t)(kk + ni * 8 * TS) * 2;
                ldsm2(bh[ni], st + OFF_BH + ro);
                ldsm2(bl[ni], st + OFF_BL + ro);
            }
#define MMA_H(BF)                                                              \
            asm volatile(                                                      \
                "mma.sync.aligned.m16n8k16.row.col.f32.f16.f16.f32 "           \
                "{%0,%1,%2,%3}, {%4,%5,%6,%7}, {%8,%9}, {%0,%1,%2,%3};"        \
                : "+f"(acc[mi][ni][0]), "+f"(acc[mi][ni][1]),                  \
                  "+f"(acc[mi][ni][2]), "+f"(acc[mi][ni][3])                   \
                : "r"(af[mi][0]), "r"(af[mi][1]),                              \
                  "r"(af[mi][2]), "r"(af[mi][3]),                              \
                  "r"(BF[ni][0]), "r"(BF[ni][1]))
#pragma unroll
            for (int mi = 0; mi < 4; mi++)
#pragma unroll
                for (int ni = 0; ni < 4; ni++) { MMA_H(bl); }
#pragma unroll
            for (int mi = 0; mi < 4; mi++)
#pragma unroll
                for (int ni = 0; ni < 4; ni++) { MMA_H(bh); }
#undef MMA_H
        }
        stage = (stage + 1 == NSTAGE) ? 0 : stage + 1;
    }

    // epilogue: bias + relu + store (m16n8 accum layout)
#pragma unroll
    for (int mi = 0; mi < 4; mi++) {
        int r0 = rowBase + wm * 64 + mi * 16 + (lane >> 2);
#pragma unroll
        for (int ni = 0; ni < 4; ni++) {
            int col = colBase + wn * 32 + ni * 8 + (lane & 3) * 2;
            float b0 = bias[col], b1v = bias[col + 1];
            if (r0 < M) {
                float2 o;
                o.x = fmaxf(acc[mi][ni][0] + b0, 0.f);
                o.y = fmaxf(acc[mi][ni][1] + b1v, 0.f);
                *(float2*)&C[(long)r0 * HIDDEN + col] = o;
            }
            if (r0 + 8 < M) {
                float2 o;
                o.x = fmaxf(acc[mi][ni][2] + b0, 0.f);
                o.y = fmaxf(acc[mi][ni][3] + b1v, 0.f);
                *(float2*)&C[(long)(r0 + 8) * HIDDEN + col] = o;
            }
        }
    }
}

// ---------------- SpMM: fp32 gather-accumulate -> single fp16 output ----------------
__device__ __forceinline__ void store_h4(__half* out, long off, float4 acc) {
    __half2 p01 = __floats2half2_rn(acc.x, acc.y);
    __half2 p23 = __floats2half2_rn(acc.z, acc.w);
    uint2 v;
    v.x = *(uint32_t*)&p01;
    v.y = *(uint32_t*)&p23;
    *(uint2*)&out[off] = v;   // 8B store, off is multiple of 4 halves -> 8B aligned
}

// 128-col: 1 warp per node (input fp32 x)
__global__ __launch_bounds__(256) void k_spmm128(const float* __restrict__ in,
                                                 __half* __restrict__ out) {
    int node = blockIdx.x * 8 + (threadIdx.x >> 5);
    if (node >= N_NODES) return;
    int c = (threadIdx.x & 31) * 4;
    int beg = node * BUCKET;
    int end = beg + g_fill[node];

    float4 acc = make_float4(0.f, 0.f, 0.f, 0.f);
    int e = beg;
    for (; e + 4 <= end; e += 4) {
        int4 p = *(const int4*)&g_csr[e];
        int4 q = *(const int4*)&g_csr[e + 2];
        float w0 = __int_as_float(p.y), w1 = __int_as_float(p.w);
        float w2 = __int_as_float(q.y), w3 = __int_as_float(q.w);
        float4 v0 = *(const float4*)&in[(long)p.x * F_IN + c];
        float4 v1 = *(const float4*)&in[(long)p.z * F_IN + c];
        float4 v2 = *(const float4*)&in[(long)q.x * F_IN + c];
        float4 v3 = *(const float4*)&in[(long)q.z * F_IN + c];
        acc.x = fmaf(v0.x, w0, acc.x); acc.y = fmaf(v0.y, w0, acc.y);
        acc.z = fmaf(v0.z, w0, acc.z); acc.w = fmaf(v0.w, w0, acc.w);
        acc.x = fmaf(v1.x, w1, acc.x); acc.y = fmaf(v1.y, w1, acc.y);
        acc.z = fmaf(v1.z, w1, acc.z); acc.w = fmaf(v1.w, w1, acc.w);
        acc.x = fmaf(v2.x, w2, acc.x); acc.y = fmaf(v2.y, w2, acc.y);
        acc.z = fmaf(v2.z, w2, acc.z); acc.w = fmaf(v2.w, w2, acc.w);
        acc.x = fmaf(v3.x, w3, acc.x); acc.y = fmaf(v3.y, w3, acc.y);
        acc.z = fmaf(v3.z, w3, acc.z); acc.w = fmaf(v3.w, w3, acc.w);
    }
    for (; e < end; e++) {
        int2 p = g_csr[e];
        float w = __int_as_float(p.y);
        float4 v = *(const float4*)&in[(long)p.x * F_IN + c];
        acc.x = fmaf(v.x, w, acc.x); acc.y = fmaf(v.y, w, acc.y);
        acc.z = fmaf(v.z, w, acc.z); acc.w = fmaf(v.w, w, acc.w);
    }
    store_h4(out, (long)node * F_IN + c, acc);
}

// 256-col: 64 threads per node (input fp32 h1)
__global__ __launch_bounds__(256) void k_spmm256(const float* __restrict__ in,
                                                 __half* __restrict__ out) {
    int node = blockIdx.x * 4 + (threadIdx.x >> 6);
    if (node >= N_NODES) return;
    int c = (threadIdx.x & 63) * 4;
    int beg = node * BUCKET;
    int end = beg + g_fill[node];

    float4 acc = make_float4(0.f, 0.f, 0.f, 0.f);
    int e = beg;
    for (; e + 4 <= end; e += 4) {
        int4 p = *(const int4*)&g_csr[e];
        int4 q = *(const int4*)&g_csr[e + 2];
        float w0 = __int_as_float(p.y), w1 = __int_as_float(p.w);
        float w2 = __int_as_float(q.y), w3 = __int_as_float(q.w);
        float4 v0 = *(const float4*)&in[(long)p.x * HIDDEN + c];
        float4 v1 = *(const float4*)&in[(long)p.z * HIDDEN + c];
        float4 v2 = *(const float4*)&in[(long)q.x * HIDDEN + c];
        float4 v3 = *(const float4*)&in[(long)q.z * HIDDEN + c];
        acc.x = fmaf(v0.x, w0, acc.x); acc.y = fmaf(v0.y, w0, acc.y);
        acc.z = fmaf(v0.z, w0, acc.z); acc.w = fmaf(v0.w, w0, acc.w);
        acc.x = fmaf(v1.x, w1, acc.x); acc.y = fmaf(v1.y, w1, acc.y);
        acc.z = fmaf(v1.z, w1, acc.z); acc.w = fmaf(v1.w, w1, acc.w);
        acc.x = fmaf(v2.x, w2, acc.x); acc.y = fmaf(v2.y, w2, acc.y);
        acc.z = fmaf(v2.z, w2, acc.z); acc.w = fmaf(v2.w, w2, acc.w);
        acc.x = fmaf(v3.x, w3, acc.x); acc.y = fmaf(v3.y, w3, acc.y);
        acc.z = fmaf(v3.z, w3, acc.z); acc.w = fmaf(v3.w, w3, acc.w);
    }
    for (; e < end; e++) {
        int2 p = g_csr[e];
        float w = __int_as_float(p.y);
        float4 v = *(const float4*)&in[(long)p.x * HIDDEN + c];
        acc.x = fmaf(v.x, w, acc.x); acc.y = fmaf(v.y, w, acc.y);
        acc.z = fmaf(v.z, w, acc.z); acc.w = fmaf(v.w, w, acc.w);
    }
    store_h4(out, (long)node * HIDDEN + c, acc);
}

// ---------------- fused pool + head ----------------
__global__ __launch_bounds__(256) void k_poolhead(const float* __restrict__ h,
                                                  const float* __restrict__ Wd,
                                                  const float* __restrict__ bd,
                                                  const float* __restrict__ Wo,
                                                  const float* __restrict__ bo,
                                                  float* __restrict__ out) {
    __shared__ float pg[HIDDEN];
    __shared__ float red[256];
    int g = blockIdx.x;
    int j = threadIdx.x;
    int beg = g_gstart[g], end = g_gstart[g + 1];

    float acc0 = 0.f, acc1 = 0.f, acc2 = 0.f, acc3 = 0.f;
    int n = beg;
    for (; n + 4 <= end; n += 4) {
        acc0 += h[(long)n * HIDDEN + j];
        acc1 += h[(long)(n + 1) * HIDDEN + j];
        acc2 += h[(long)(n + 2) * HIDDEN + j];
        acc3 += h[(long)(n + 3) * HIDDEN + j];
    }
    for (; n < end; n++) acc0 += h[(long)n * HIDDEN + j];
    pg[j] = (acc0 + acc1) + (acc2 + acc3);
    __syncthreads();

    float acc = 0.f;
#pragma unroll 8
    for (int k = 0; k < HIDDEN; k++)
        acc = fmaf(pg[k], Wd[k * HIDDEN + j], acc);
    float v = fmaxf(acc + bd[j], 0.f);
    red[j] = v * Wo[j];
    __syncthreads();
    for (int s = 128; s > 0; s >>= 1) {
        if (j < s) red[j] += red[j + s];
        __syncthreads();
    }
    if (j == 0) out[g] = red[0] + bo[0];
}

// ---------------- launch ----------------
extern "C" void kernel_launch(void* const* d_in, const int* in_sizes, int n_in,
                              void* d_out, int out_size) {
    const float* x        = (const float*)d_in[0];
    const int*   edge_src = (const int*)d_in[1];
    const int*   edge_dst = (const int*)d_in[2];
    const float* edge_w   = (const float*)d_in[3];
    const int*   seg_ids  = (const int*)d_in[4];
    const float* W1       = (const float*)d_in[5];
    const float* b1       = (const float*)d_in[6];
    const float* W2       = (const float*)d_in[7];
    const float* b2       = (const float*)d_in[8];
    const float* Wd       = (const float*)d_in[9];
    const float* bd       = (const float*)d_in[10];
    const float* Wo       = (const float*)d_in[11];
    const float* bo       = (const float*)d_in[12];
    float* out = (float*)d_out;

    float* bufA; cudaGetSymbolAddress((void**)&bufA, g_bufA);
    float* bufB; cudaGetSymbolAddress((void**)&bufB, g_bufB);
    __half* sH;  cudaGetSymbolAddress((void**)&sH,  g_sH);
    __half* w1h; cudaGetSymbolAddress((void**)&w1h, g_W1h);
    __half* w1l; cudaGetSymbolAddress((void**)&w1l, g_W1l);
    __half* w2h; cudaGetSymbolAddress((void**)&w2h, g_W2h);
    __half* w2l; cudaGetSymbolAddress((void**)&w2l, g_W2l);

    cudaFuncSetAttribute(k_gemm_pipe, cudaFuncAttributeMaxDynamicSharedMemorySize, GEMM_SMEM);

    // setup + scatter
    k_setup<<<(HIDDEN * HIDDEN + 255) / 256, 256>>>(seg_ids, W1, W2);
    k_scatter<<<(N_EDGES + 255) / 256, 256>>>(edge_src, edge_dst, edge_w);

    dim3 gemmGrid(HIDDEN / GBN, (N_NODES + GBM - 1) / GBM);

    // layer 1: s1 = A@x (fp16); h1 = relu(s1 @ W1 + b1)  [fp32]
    k_spmm128<<<(N_NODES + 7) / 8, 256>>>(x, sH);
    k_gemm_pipe<<<gemmGrid, 256, GEMM_SMEM>>>(sH, F_IN, w1h, w1l, b1, bufA, N_NODES);

    // layer 2: s2 = A@h1 (fp16); h2 = relu(s2 @ W2 + b2)  [fp32]
    k_spmm256<<<(N_NODES + 3) / 4, 256>>>(bufA, sH);
    k_gemm_pipe<<<gemmGrid, 256, GEMM_SMEM>>>(sH, HIDDEN, w2h, w2l, b2, bufB, N_NODES);

    // fused pool + head
    k_poolhead<<<N_GRAPHS, HIDDEN>>>(bufB, Wd, bd, Wo, bo, out);
}